// round 8
// baseline (speedup 1.0000x reference)
#include <cuda_runtime.h>
#include <cuda_bf16.h>
#include <mma.h>
#include <cstdint>

using namespace nvcuda;

// ============================================================================
// Problem constants
// ============================================================================
#define D_MODEL   512
#define MAXLEN    1024
#define M_TOTAL   65536      // 128 batch * 512 parts
#define KDIM      512
#define MCTA      64         // CTA M tile
#define NCTA      128        // CTA N tile

// ============================================================================
// Device globals (no cudaMalloc allowed)
// ============================================================================
__device__ __align__(16) float g_E[MAXLEN * D_MODEL];   // enc @ W1 + 0.5*b (2 MB)
__device__ int g_is64;    // index dtype flag
__device__ int g_swap;    // 0: cand1=enc,cand2=W ; 1: cand1=W,cand2=enc

// ============================================================================
// Kernel 0: runtime input identification.
//  - is64: int64 indices have all-zero odd 32-bit words (values < 1024).
//  - swap: encoding row 0 is exactly [0,1,0,1,...] (sin0/cos0).
// Reads only the first 256 KB of p — safe for int32 (256 KB) and int64 (512 KB).
// ============================================================================
__global__ void detect_kernel(const int* __restrict__ p, const float* __restrict__ cand1) {
    __shared__ int any;
    if (threadIdx.x == 0) any = 0;
    __syncthreads();
    int acc = 0;
    for (int i = threadIdx.x; i < 32768; i += 256) acc |= p[2 * i + 1];
    if (acc) atomicOr(&any, 1);
    __syncthreads();
    if (threadIdx.x == 0) {
        g_is64 = (any == 0) ? 1 : 0;
        bool is_enc = (cand1[0] == 0.0f) && (cand1[1] == 1.0f) &&
                      (cand1[2] == 0.0f) && (cand1[3] == 1.0f);
        g_swap = is_enc ? 0 : 1;
    }
}

// ============================================================================
// Kernel 1: E[1024,512] = enc @ W[0:512,:] + 0.5*b  (fp32 SGEMM, small)
// ============================================================================
__global__ __launch_bounds__(256)
void compute_E_kernel(const float* __restrict__ cand1, const float* __restrict__ cand2,
                      const float* __restrict__ bias) {
    const float* enc = g_swap ? cand2 : cand1;
    const float* W   = g_swap ? cand1 : cand2;
    __shared__ float As[32][68];
    __shared__ float Bs[32][68];
    const int m0 = blockIdx.x * 64;
    const int n0 = blockIdx.y * 64;
    const int t = threadIdx.x;
    const int tm = (t & 15) * 4;
    const int tn = (t >> 4) * 4;
    float acc[4][4] = {};
    for (int k0 = 0; k0 < 512; k0 += 32) {
        {
            int rr = t >> 2, cc = (t & 3) * 8;
            const float* s = enc + (size_t)(m0 + rr) * 512 + k0 + cc;
            #pragma unroll
            for (int j = 0; j < 8; j++) As[cc + j][rr] = s[j];
        }
        {
            int rr = t >> 3, cc = (t & 7) * 8;
            const float* s = W + (size_t)(k0 + rr) * 512 + n0 + cc;
            #pragma unroll
            for (int j = 0; j < 8; j++) Bs[rr][cc + j] = s[j];
        }
        __syncthreads();
        #pragma unroll
        for (int kk = 0; kk < 32; kk++) {
            float a[4], b[4];
            #pragma unroll
            for (int i = 0; i < 4; i++) a[i] = As[kk][tm + i];
            #pragma unroll
            for (int i = 0; i < 4; i++) b[i] = Bs[kk][tn + i];
            #pragma unroll
            for (int i = 0; i < 4; i++)
                #pragma unroll
                for (int j = 0; j < 4; j++)
                    acc[i][j] += a[i] * b[j];
        }
        __syncthreads();
    }
    #pragma unroll
    for (int i = 0; i < 4; i++) {
        float4 o;
        o.x = acc[i][0] + 0.5f * bias[n0 + tn + 0];
        o.y = acc[i][1] + 0.5f * bias[n0 + tn + 1];
        o.z = acc[i][2] + 0.5f * bias[n0 + tn + 2];
        o.w = acc[i][3] + 0.5f * bias[n0 + tn + 3];
        *(float4*)&g_E[(size_t)(m0 + tm + i) * 512 + n0 + tn] = o;
    }
}

// ============================================================================
// Kernel 2: main GEMM via nvcuda::wmma (tf32 m16n16k8) + fused gather epilogue.
// CTA tile 64x128, 8 warps as 2x4, each warp 32x32 (2x2 fragments).
// Smem: As[64][36] + Bs[32][132] (row-major, padded) = 6528 floats;
//       epilogue staging reuses the same 9216-float buffer (per warp 32x36).
// W2 = W[512:1024,:] read RAW from the input weight (no preprocessed image).
// Epilogue: out = acc + E[dfn[m]] + E[dfn_fa[m]]  (bias folded as 0.5b in E;
//           indices masked to [0,1024) -> cannot fault).
// ============================================================================
__global__ __launch_bounds__(256, 2)
void gemm_wmma(const float* __restrict__ latent,
               const float* __restrict__ cand1,
               const float* __restrict__ cand2,
               const void* __restrict__ dfnp,
               const void* __restrict__ dfap,
               float* __restrict__ out) {
    const float* W = g_swap ? cand1 : cand2;   // the raw (1024,512) weight
    __shared__ float smem[9216];
    float* As = smem;              // [64][36]
    float* Bs = smem + 2304;       // [32][132]

    const int t    = threadIdx.x;
    const int wid  = t >> 5;
    const int lane = t & 31;
    const int wr   = wid >> 2;     // 0..1
    const int wc   = wid & 3;      // 0..3
    const int n0   = blockIdx.x * NCTA;   // 0..384
    const int m0   = blockIdx.y * MCTA;   // 0..65472

    wmma::fragment<wmma::accumulator, 16, 16, 8, float> acc[2][2];
    #pragma unroll
    for (int i = 0; i < 2; i++)
        #pragma unroll
        for (int j = 0; j < 2; j++)
            wmma::fill_fragment(acc[i][j], 0.0f);

    for (int k0 = 0; k0 < KDIM; k0 += 32) {
        // ---- A tile: latent[m0..m0+63][k0..k0+31] -> As[64][36], coalesced ----
        #pragma unroll
        for (int i = 0; i < 2; i++) {
            int f = i * 256 + t;            // 0..511
            int r = f >> 3, cq = f & 7;     // r 0..63, cq 0..7
            float4 v = *(const float4*)(latent + (size_t)(m0 + r) * KDIM + k0 + cq * 4);
            *(float4*)(As + r * 36 + cq * 4) = v;
        }
        // ---- B tile: W[512+k0 .. +31][n0..n0+127] -> Bs[32][132], coalesced ----
        #pragma unroll
        for (int i = 0; i < 4; i++) {
            int f = i * 256 + t;            // 0..1023
            int r = f >> 5, cq = f & 31;    // r 0..31, cq 0..31
            float4 v = *(const float4*)(W + (size_t)(512 + k0 + r) * 512 + n0 + cq * 4);
            *(float4*)(Bs + r * 132 + cq * 4) = v;
        }
        __syncthreads();

        // ---- wmma: 4 k-steps of 8 ----
        #pragma unroll
        for (int ks = 0; ks < 4; ks++) {
            wmma::fragment<wmma::matrix_a, 16, 16, 8, wmma::precision::tf32, wmma::row_major> a[2];
            wmma::fragment<wmma::matrix_b, 16, 16, 8, wmma::precision::tf32, wmma::row_major> b[2];
            #pragma unroll
            for (int ri = 0; ri < 2; ri++) {
                wmma::load_matrix_sync(a[ri], As + (wr * 32 + ri * 16) * 36 + ks * 8, 36);
                #pragma unroll
                for (int x = 0; x < a[ri].num_elements; x++)
                    a[ri].x[x] = wmma::__float_to_tf32(a[ri].x[x]);
            }
            #pragma unroll
            for (int ci = 0; ci < 2; ci++) {
                wmma::load_matrix_sync(b[ci], Bs + (ks * 8) * 132 + wc * 32 + ci * 16, 132);
                #pragma unroll
                for (int x = 0; x < b[ci].num_elements; x++)
                    b[ci].x[x] = wmma::__float_to_tf32(b[ci].x[x]);
            }
            #pragma unroll
            for (int ri = 0; ri < 2; ri++)
                #pragma unroll
                for (int ci = 0; ci < 2; ci++)
                    wmma::mma_sync(acc[ri][ci], a[ri], b[ci], acc[ri][ci]);
        }
        __syncthreads();
    }

    // ---- Epilogue: stage acc to smem (per-warp 32x36), add E gathers, store ----
    float* wbuf = smem + wid * 1152;   // 32*36 floats per warp
    #pragma unroll
    for (int ri = 0; ri < 2; ri++)
        #pragma unroll
        for (int ci = 0; ci < 2; ci++)
            wmma::store_matrix_sync(wbuf + ri * 576 + ci * 16, acc[ri][ci], 36,
                                    wmma::mem_row_major);
    __syncwarp();

    const int m = m0 + wr * 32 + lane;          // this lane's output row
    int i1, i2;
    if (g_is64) {
        i1 = (int)((const long long*)dfnp)[m] & (MAXLEN - 1);
        i2 = (int)((const long long*)dfap)[m] & (MAXLEN - 1);
    } else {
        i1 = ((const int*)dfnp)[m] & (MAXLEN - 1);
        i2 = ((const int*)dfap)[m] & (MAXLEN - 1);
    }
    const float* e1 = g_E + (size_t)i1 * D_MODEL;
    const float* e2 = g_E + (size_t)i2 * D_MODEL;
    float* orow = out + (size_t)m * D_MODEL;
    const int cbase = n0 + wc * 32;
    #pragma unroll
    for (int cq = 0; cq < 8; cq++) {
        const int c = cbase + cq * 4;
        float4 v  = *(float4*)(wbuf + lane * 36 + cq * 4);
        float4 a1 = *(const float4*)(e1 + c);
        float4 a2 = *(const float4*)(e2 + c);
        v.x += a1.x + a2.x;  v.y += a1.y + a2.y;
        v.z += a1.z + a2.z;  v.w += a1.w + a2.w;
        *(float4*)(orow + c) = v;
    }
}

// ============================================================================
// Host launcher — rank-based classification (robust to size conventions and
// ordering). enc vs W disambiguated on-device; dfn vs dfn_fa symmetric.
// ============================================================================
extern "C" void kernel_launch(void* const* d_in, const int* in_sizes, int n_in,
                              void* d_out, int out_size) {
    int order[16];
    int n = (n_in < 16) ? n_in : 16;
    for (int i = 0; i < n; i++) order[i] = i;
    for (int i = 1; i < n; i++) {
        int key = order[i];
        long long ks = in_sizes[key];
        int j = i - 1;
        while (j >= 0 && (long long)in_sizes[order[j]] > ks) {
            order[j + 1] = order[j];
            j--;
        }
        order[j + 1] = key;
    }

    const void*  dfn;
    const void*  dfa;
    const float* latent;
    const float* cand1;
    const float* cand2;
    const float* bias;

    if (n >= 6) {
        bias   = (const float*)d_in[order[0]];
        dfn    = d_in[order[1]];
        dfa    = d_in[order[2]];
        cand1  = (const float*)d_in[order[3]];
        cand2  = (const float*)d_in[order[4]];
        latent = (const float*)d_in[order[n - 1]];
    } else {
        dfn    = d_in[0];
        dfa    = d_in[1];
        latent = (const float*)d_in[2];
        cand1  = (const float*)d_in[3];
        cand2  = (const float*)d_in[4];
        bias   = (const float*)d_in[5];
    }

    detect_kernel<<<1, 256>>>((const int*)dfn, cand1);
    compute_E_kernel<<<dim3(16, 8), 256>>>(cand1, cand2, bias);

    dim3 grid(D_MODEL / NCTA, M_TOTAL / MCTA);   // (4, 1024), n fastest
    gemm_wmma<<<grid, 256>>>(latent, cand1, cand2, dfn, dfa, (float*)d_out);
}

// round 9
// speedup vs baseline: 1.2144x; 1.2144x over previous
#include <cuda_runtime.h>
#include <cuda_bf16.h>
#include <mma.h>
#include <cstdint>

using namespace nvcuda;

// ============================================================================
// Problem constants
// ============================================================================
#define D_MODEL   512
#define MAXLEN    1024
#define M_TOTAL   65536      // 128 batch * 512 parts
#define KDIM      512
#define MCTA      128        // CTA M tile
#define NCTA      128        // CTA N tile
#define KSTAGE    32
#define NSTAGES   16         // 512/32
#define THREADS   256

// Stage geometry (floats)
#define A_LD      36                     // padded row stride of A tile
#define B_LD      132                    // padded row stride of B tile
#define A_STG     (MCTA * A_LD)          // 4608
#define B_STG     (KSTAGE * B_LD)        // 4224
#define STG_FLOATS (A_STG + B_STG)       // 8832
#define SMEM_FLOATS (2 * STG_FLOATS)     // 17664
#define SMEM_BYTES (SMEM_FLOATS * 4)     // 70656

// ============================================================================
// Device globals (no cudaMalloc allowed)
// ============================================================================
__device__ __align__(16) float g_E[MAXLEN * D_MODEL];   // enc @ W1 + 0.5*b (2 MB)
__device__ int g_is64;    // index dtype flag
__device__ int g_swap;    // 0: cand1=enc,cand2=W ; 1: cand1=W,cand2=enc

// ============================================================================
// cp.async helpers
// ============================================================================
__device__ __forceinline__ void cp16(float* dst_smem, const float* src) {
    uint32_t d = (uint32_t)__cvta_generic_to_shared(dst_smem);
    asm volatile("cp.async.cg.shared.global [%0], [%1], 16;" :: "r"(d), "l"(src));
}
#define CP_COMMIT() asm volatile("cp.async.commit_group;" ::: "memory")
#define CP_WAIT(n)  asm volatile("cp.async.wait_group %0;" :: "n"(n) : "memory")

// ============================================================================
// Kernel 0: runtime input identification (16 KB of index reads).
// ============================================================================
__global__ void detect_kernel(const int* __restrict__ p, const float* __restrict__ cand1) {
    __shared__ int any;
    if (threadIdx.x == 0) any = 0;
    __syncthreads();
    int acc = 0;
    for (int i = threadIdx.x; i < 4096; i += 256) acc |= p[2 * i + 1];
    if (acc) atomicOr(&any, 1);
    __syncthreads();
    if (threadIdx.x == 0) {
        g_is64 = (any == 0) ? 1 : 0;
        bool is_enc = (cand1[0] == 0.0f) && (cand1[1] == 1.0f) &&
                      (cand1[2] == 0.0f) && (cand1[3] == 1.0f);
        g_swap = is_enc ? 0 : 1;
    }
}

// ============================================================================
// Kernel 1: E[1024,512] = enc @ W[0:512,:] + 0.5*b  (fp32 SGEMM, small)
// ============================================================================
__global__ __launch_bounds__(256)
void compute_E_kernel(const float* __restrict__ cand1, const float* __restrict__ cand2,
                      const float* __restrict__ bias) {
    const float* enc = g_swap ? cand2 : cand1;
    const float* W   = g_swap ? cand1 : cand2;
    __shared__ float As[32][68];
    __shared__ float Bs[32][68];
    const int m0 = blockIdx.x * 64;
    const int n0 = blockIdx.y * 64;
    const int t = threadIdx.x;
    const int tm = (t & 15) * 4;
    const int tn = (t >> 4) * 4;
    float acc[4][4] = {};
    for (int k0 = 0; k0 < 512; k0 += 32) {
        {
            int rr = t >> 2, cc = (t & 3) * 8;
            const float* s = enc + (size_t)(m0 + rr) * 512 + k0 + cc;
            #pragma unroll
            for (int j = 0; j < 8; j++) As[cc + j][rr] = s[j];
        }
        {
            int rr = t >> 3, cc = (t & 7) * 8;
            const float* s = W + (size_t)(k0 + rr) * 512 + n0 + cc;
            #pragma unroll
            for (int j = 0; j < 8; j++) Bs[rr][cc + j] = s[j];
        }
        __syncthreads();
        #pragma unroll
        for (int kk = 0; kk < 32; kk++) {
            float a[4], b[4];
            #pragma unroll
            for (int i = 0; i < 4; i++) a[i] = As[kk][tm + i];
            #pragma unroll
            for (int i = 0; i < 4; i++) b[i] = Bs[kk][tn + i];
            #pragma unroll
            for (int i = 0; i < 4; i++)
                #pragma unroll
                for (int j = 0; j < 4; j++)
                    acc[i][j] += a[i] * b[j];
        }
        __syncthreads();
    }
    #pragma unroll
    for (int i = 0; i < 4; i++) {
        float4 o;
        o.x = acc[i][0] + 0.5f * bias[n0 + tn + 0];
        o.y = acc[i][1] + 0.5f * bias[n0 + tn + 1];
        o.z = acc[i][2] + 0.5f * bias[n0 + tn + 2];
        o.w = acc[i][3] + 0.5f * bias[n0 + tn + 3];
        *(float4*)&g_E[(size_t)(m0 + tm + i) * 512 + n0 + tn] = o;
    }
}

// ============================================================================
// Kernel 2: main GEMM (wmma tf32 m16n16k8) + fused gather epilogue.
// CTA 128x128, 8 warps (2x4), warp tile 64x32 (4x2 fragments).
// 2-stage cp.async pipeline, dynamic smem 70656 B, 2 CTAs/SM.
// ============================================================================
__global__ __launch_bounds__(THREADS, 2)
void gemm_wmma(const float* __restrict__ latent,
               const float* __restrict__ cand1,
               const float* __restrict__ cand2,
               const void* __restrict__ dfnp,
               const void* __restrict__ dfap,
               float* __restrict__ out) {
    const float* W = g_swap ? cand1 : cand2;   // raw (1024,512) weight
    extern __shared__ __align__(16) float smem[];

    const int t    = threadIdx.x;
    const int wid  = t >> 5;
    const int lane = t & 31;
    const int wr   = wid >> 2;     // 0..1 (64-row half)
    const int wc   = wid & 3;      // 0..3 (32-col quarter)
    const int n0   = blockIdx.x * NCTA;   // 0..384
    const int m0   = blockIdx.y * MCTA;   // 0..65408

    // ---- cp.async stage issue: A 128x32, B 32x128 (float4 granularity) ----
    #define ISSUE_STAGE(kc_) do {                                              \
        float* as = smem + ((kc_) & 1) * STG_FLOATS;                           \
        float* bs = as + A_STG;                                                \
        const int k0_ = (kc_) * KSTAGE;                                        \
        _Pragma("unroll")                                                      \
        for (int i = 0; i < 4; i++) {                                          \
            int f = i * 256 + t;            /* 0..1023 */                      \
            int r = f >> 3, cq = f & 7;     /* A: r 0..127, cq 0..7 */         \
            cp16(as + r * A_LD + cq * 4,                                       \
                 latent + (size_t)(m0 + r) * KDIM + k0_ + cq * 4);             \
        }                                                                      \
        _Pragma("unroll")                                                      \
        for (int i = 0; i < 4; i++) {                                          \
            int f = i * 256 + t;            /* 0..1023 */                      \
            int r = f >> 5, cq = f & 31;    /* B: r 0..31, cq 0..31 */         \
            cp16(bs + r * B_LD + cq * 4,                                       \
                 W + (size_t)(512 + k0_ + r) * 512 + n0 + cq * 4);             \
        }                                                                      \
        CP_COMMIT();                                                           \
    } while (0)

    wmma::fragment<wmma::accumulator, 16, 16, 8, float> acc[4][2];
    #pragma unroll
    for (int i = 0; i < 4; i++)
        #pragma unroll
        for (int j = 0; j < 2; j++)
            wmma::fill_fragment(acc[i][j], 0.0f);

    ISSUE_STAGE(0);

    for (int kc = 0; kc < NSTAGES; ++kc) {
        if (kc + 1 < NSTAGES) {
            ISSUE_STAGE(kc + 1);
            CP_WAIT(1);
        } else {
            CP_WAIT(0);
        }
        __syncthreads();

        const float* as = smem + (kc & 1) * STG_FLOATS;
        const float* bs = as + A_STG;

        #pragma unroll
        for (int ks = 0; ks < 4; ks++) {
            wmma::fragment<wmma::matrix_a, 16, 16, 8, wmma::precision::tf32, wmma::row_major> a[4];
            wmma::fragment<wmma::matrix_b, 16, 16, 8, wmma::precision::tf32, wmma::row_major> b[2];
            #pragma unroll
            for (int ri = 0; ri < 4; ri++) {
                wmma::load_matrix_sync(a[ri], as + (wr * 64 + ri * 16) * A_LD + ks * 8, A_LD);
                #pragma unroll
                for (int x = 0; x < a[ri].num_elements; x++)
                    a[ri].x[x] = wmma::__float_to_tf32(a[ri].x[x]);
            }
            #pragma unroll
            for (int ci = 0; ci < 2; ci++) {
                wmma::load_matrix_sync(b[ci], bs + (ks * 8) * B_LD + wc * 32 + ci * 16, B_LD);
                #pragma unroll
                for (int x = 0; x < b[ci].num_elements; x++)
                    b[ci].x[x] = wmma::__float_to_tf32(b[ci].x[x]);
            }
            #pragma unroll
            for (int ri = 0; ri < 4; ri++)
                #pragma unroll
                for (int ci = 0; ci < 2; ci++)
                    wmma::mma_sync(acc[ri][ci], a[ri], b[ci], acc[ri][ci]);
        }
        __syncthreads();
    }

    // ---- Epilogue: two 32-row halves per warp; stage via smem, add E gathers ----
    // (safe to reuse stage buffers: trailing __syncthreads above)
    float* wbuf = smem + wid * 1152;   // 32 rows x 36 per warp (9216 total)
    const int is64 = g_is64;
    #pragma unroll
    for (int h = 0; h < 2; h++) {
        #pragma unroll
        for (int rh = 0; rh < 2; rh++)
            #pragma unroll
            for (int ci = 0; ci < 2; ci++)
                wmma::store_matrix_sync(wbuf + rh * 16 * 36 + ci * 16,
                                        acc[h * 2 + rh][ci], 36, wmma::mem_row_major);
        __syncwarp();

        const int m = m0 + wr * 64 + h * 32 + lane;
        int i1, i2;
        if (is64) {
            i1 = (int)((const long long*)dfnp)[m] & (MAXLEN - 1);
            i2 = (int)((const long long*)dfap)[m] & (MAXLEN - 1);
        } else {
            i1 = ((const int*)dfnp)[m] & (MAXLEN - 1);
            i2 = ((const int*)dfap)[m] & (MAXLEN - 1);
        }
        const float* e1 = g_E + (size_t)i1 * D_MODEL;
        const float* e2 = g_E + (size_t)i2 * D_MODEL;
        float* orow = out + (size_t)m * D_MODEL;
        const int cbase = n0 + wc * 32;
        #pragma unroll
        for (int cq = 0; cq < 8; cq++) {
            const int c = cbase + cq * 4;
            float4 v  = *(float4*)(wbuf + lane * 36 + cq * 4);
            float4 a1 = *(const float4*)(e1 + c);
            float4 a2 = *(const float4*)(e2 + c);
            v.x += a1.x + a2.x;  v.y += a1.y + a2.y;
            v.z += a1.z + a2.z;  v.w += a1.w + a2.w;
            *(float4*)(orow + c) = v;
        }
        __syncwarp();
    }
    #undef ISSUE_STAGE
}

// ============================================================================
// Host launcher — rank-based classification (robust to size conventions and
// ordering). enc vs W disambiguated on-device; dfn vs dfn_fa symmetric.
// ============================================================================
extern "C" void kernel_launch(void* const* d_in, const int* in_sizes, int n_in,
                              void* d_out, int out_size) {
    int order[16];
    int n = (n_in < 16) ? n_in : 16;
    for (int i = 0; i < n; i++) order[i] = i;
    for (int i = 1; i < n; i++) {
        int key = order[i];
        long long ks = in_sizes[key];
        int j = i - 1;
        while (j >= 0 && (long long)in_sizes[order[j]] > ks) {
            order[j + 1] = order[j];
            j--;
        }
        order[j + 1] = key;
    }

    const void*  dfn;
    const void*  dfa;
    const float* latent;
    const float* cand1;
    const float* cand2;
    const float* bias;

    if (n >= 6) {
        bias   = (const float*)d_in[order[0]];
        dfn    = d_in[order[1]];
        dfa    = d_in[order[2]];
        cand1  = (const float*)d_in[order[3]];
        cand2  = (const float*)d_in[order[4]];
        latent = (const float*)d_in[order[n - 1]];
    } else {
        dfn    = d_in[0];
        dfa    = d_in[1];
        latent = (const float*)d_in[2];
        cand1  = (const float*)d_in[3];
        cand2  = (const float*)d_in[4];
        bias   = (const float*)d_in[5];
    }

    detect_kernel<<<1, 256>>>((const int*)dfn, cand1);
    compute_E_kernel<<<dim3(16, 8), 256>>>(cand1, cand2, bias);

    cudaFuncSetAttribute(gemm_wmma, cudaFuncAttributeMaxDynamicSharedMemorySize, SMEM_BYTES);

    dim3 grid(D_MODEL / NCTA, M_TOTAL / MCTA);   // (4, 512), n fastest
    gemm_wmma<<<grid, THREADS, SMEM_BYTES>>>(latent, cand1, cand2, dfn, dfa, (float*)d_out);
}

// round 10
// speedup vs baseline: 1.3823x; 1.1382x over previous
#include <cuda_runtime.h>
#include <cuda_bf16.h>
#include <mma.h>
#include <cstdint>

using namespace nvcuda;

// ============================================================================
// Problem constants
// ============================================================================
#define D_MODEL   512
#define MAXLEN    1024
#define M_TOTAL   65536      // 128 batch * 512 parts
#define KDIM      512
#define MCTA      128        // CTA M tile
#define NCTA      128        // CTA N tile
#define KSTAGE    32
#define NSTAGES   16         // 512/32
#define THREADS   128        // 4 warps (2x2), warp tile 64x64

// Stage geometry (floats)
#define A_LD      36                     // padded row stride of A tile
#define B_LD      132                    // padded row stride of B tile
#define A_STG     (MCTA * A_LD)          // 4608
#define B_STG     (KSTAGE * B_LD)        // 4224
#define STG_FLOATS (A_STG + B_STG)       // 8832
#define SMEM_FLOATS (2 * STG_FLOATS)     // 17664
#define SMEM_BYTES (SMEM_FLOATS * 4)     // 70656

// Epilogue staging: per-warp 32 rows x 68 (padded) floats
#define EPI_LD    68

// ============================================================================
// Device globals (no cudaMalloc allowed)
// ============================================================================
__device__ __align__(16) float g_E[MAXLEN * D_MODEL];    // enc @ W1 + 0.5*b (2 MB)
__device__ __align__(16) float g_Wt[KDIM * D_MODEL];     // W2 tf32-rounded (1 MB)
__device__ int g_is64;    // index dtype flag
__device__ int g_swap;    // 0: cand1=enc,cand2=W ; 1: cand1=W,cand2=enc

// ============================================================================
// helpers
// ============================================================================
__device__ __forceinline__ uint32_t to_tf32(float x) {
    uint32_t y;
    asm("cvt.rna.tf32.f32 %0, %1;" : "=r"(y) : "f"(x));
    return y;
}
__device__ __forceinline__ void cp16(float* dst_smem, const float* src) {
    uint32_t d = (uint32_t)__cvta_generic_to_shared(dst_smem);
    asm volatile("cp.async.cg.shared.global [%0], [%1], 16;" :: "r"(d), "l"(src));
}
#define CP_COMMIT() asm volatile("cp.async.commit_group;" ::: "memory")
#define CP_WAIT(n)  asm volatile("cp.async.wait_group %0;" :: "n"(n) : "memory")

// ============================================================================
// Kernel 0: runtime input identification (16 KB of index reads).
// ============================================================================
__global__ void detect_kernel(const int* __restrict__ p, const float* __restrict__ cand1) {
    __shared__ int any;
    if (threadIdx.x == 0) any = 0;
    __syncthreads();
    int acc = 0;
    for (int i = threadIdx.x; i < 4096; i += 256) acc |= p[2 * i + 1];
    if (acc) atomicOr(&any, 1);
    __syncthreads();
    if (threadIdx.x == 0) {
        g_is64 = (any == 0) ? 1 : 0;
        bool is_enc = (cand1[0] == 0.0f) && (cand1[1] == 1.0f) &&
                      (cand1[2] == 0.0f) && (cand1[3] == 1.0f);
        g_swap = is_enc ? 0 : 1;
    }
}

// ============================================================================
// Kernel 1: pre-round W2 = W[512:1024,:] to tf32 (exact RNE), row-major copy.
// ============================================================================
__global__ void w2_tf32_kernel(const float* __restrict__ cand1,
                               const float* __restrict__ cand2) {
    const float* W = g_swap ? cand1 : cand2;
    int idx = blockIdx.x * blockDim.x + threadIdx.x;
    if (idx >= KDIM * D_MODEL) return;
    g_Wt[idx] = __uint_as_float(to_tf32(W[(size_t)(512 + (idx >> 9)) * 512 + (idx & 511)]));
}

// ============================================================================
// Kernel 2: E[1024,512] = enc @ W[0:512,:] + 0.5*b  (fp32 SGEMM, small)
// ============================================================================
__global__ __launch_bounds__(256)
void compute_E_kernel(const float* __restrict__ cand1, const float* __restrict__ cand2,
                      const float* __restrict__ bias) {
    const float* enc = g_swap ? cand2 : cand1;
    const float* W   = g_swap ? cand1 : cand2;
    __shared__ float As[32][68];
    __shared__ float Bs[32][68];
    const int m0 = blockIdx.x * 64;
    const int n0 = blockIdx.y * 64;
    const int t = threadIdx.x;
    const int tm = (t & 15) * 4;
    const int tn = (t >> 4) * 4;
    float acc[4][4] = {};
    for (int k0 = 0; k0 < 512; k0 += 32) {
        {
            int rr = t >> 2, cc = (t & 3) * 8;
            const float* s = enc + (size_t)(m0 + rr) * 512 + k0 + cc;
            #pragma unroll
            for (int j = 0; j < 8; j++) As[cc + j][rr] = s[j];
        }
        {
            int rr = t >> 3, cc = (t & 7) * 8;
            const float* s = W + (size_t)(k0 + rr) * 512 + n0 + cc;
            #pragma unroll
            for (int j = 0; j < 8; j++) Bs[rr][cc + j] = s[j];
        }
        __syncthreads();
        #pragma unroll
        for (int kk = 0; kk < 32; kk++) {
            float a[4], b[4];
            #pragma unroll
            for (int i = 0; i < 4; i++) a[i] = As[kk][tm + i];
            #pragma unroll
            for (int i = 0; i < 4; i++) b[i] = Bs[kk][tn + i];
            #pragma unroll
            for (int i = 0; i < 4; i++)
                #pragma unroll
                for (int j = 0; j < 4; j++)
                    acc[i][j] += a[i] * b[j];
        }
        __syncthreads();
    }
    #pragma unroll
    for (int i = 0; i < 4; i++) {
        float4 o;
        o.x = acc[i][0] + 0.5f * bias[n0 + tn + 0];
        o.y = acc[i][1] + 0.5f * bias[n0 + tn + 1];
        o.z = acc[i][2] + 0.5f * bias[n0 + tn + 2];
        o.w = acc[i][3] + 0.5f * bias[n0 + tn + 3];
        *(float4*)&g_E[(size_t)(m0 + tm + i) * 512 + n0 + tn] = o;
    }
}

// ============================================================================
// Kernel 3: main GEMM (wmma tf32 m16n16k8) + fused gather epilogue.
// CTA 128x128, 4 warps (2x2), warp tile 64x64 (4x4 fragments).
// 2-stage cp.async pipeline. NO in-loop tf32 conversion:
//   - B comes from g_Wt (pre-rounded RNE)
//   - A is fed raw fp32 (HMMA.TF32 truncates low mantissa bits)
// ============================================================================
__global__ __launch_bounds__(THREADS, 2)
void gemm_wmma(const float* __restrict__ latent,
               const void* __restrict__ dfnp,
               const void* __restrict__ dfap,
               float* __restrict__ out) {
    extern __shared__ __align__(16) float smem[];

    const int t    = threadIdx.x;
    const int wid  = t >> 5;
    const int lane = t & 31;
    const int wr   = wid >> 1;     // 0..1 (64-row half)
    const int wc   = wid & 1;      // 0..1 (64-col half)
    const int n0   = blockIdx.x * NCTA;   // 0..384
    const int m0   = blockIdx.y * MCTA;   // 0..65408

    #define ISSUE_STAGE(kc_) do {                                              \
        float* as = smem + ((kc_) & 1) * STG_FLOATS;                           \
        float* bs = as + A_STG;                                                \
        const int k0_ = (kc_) * KSTAGE;                                        \
        _Pragma("unroll")                                                      \
        for (int i = 0; i < 8; i++) {                                          \
            int f = i * 128 + t;            /* 0..1023 */                      \
            int r = f >> 3, cq = f & 7;     /* A: r 0..127, cq 0..7 */         \
            cp16(as + r * A_LD + cq * 4,                                       \
                 latent + (size_t)(m0 + r) * KDIM + k0_ + cq * 4);             \
        }                                                                      \
        _Pragma("unroll")                                                      \
        for (int i = 0; i < 8; i++) {                                          \
            int f = i * 128 + t;            /* 0..1023 */                      \
            int r = f >> 5, cq = f & 31;    /* B: r 0..31, cq 0..31 */         \
            cp16(bs + r * B_LD + cq * 4,                                       \
                 g_Wt + (size_t)(k0_ + r) * 512 + n0 + cq * 4);                \
        }                                                                      \
        CP_COMMIT();                                                           \
    } while (0)

    wmma::fragment<wmma::accumulator, 16, 16, 8, float> acc[4][4];
    #pragma unroll
    for (int i = 0; i < 4; i++)
        #pragma unroll
        for (int j = 0; j < 4; j++)
            wmma::fill_fragment(acc[i][j], 0.0f);

    ISSUE_STAGE(0);

    for (int kc = 0; kc < NSTAGES; ++kc) {
        if (kc + 1 < NSTAGES) {
            ISSUE_STAGE(kc + 1);
            CP_WAIT(1);
        } else {
            CP_WAIT(0);
        }
        __syncthreads();

        const float* as = smem + (kc & 1) * STG_FLOATS;
        const float* bs = as + A_STG;

        #pragma unroll
        for (int ks = 0; ks < 4; ks++) {
            wmma::fragment<wmma::matrix_a, 16, 16, 8, wmma::precision::tf32, wmma::row_major> a[4];
            wmma::fragment<wmma::matrix_b, 16, 16, 8, wmma::precision::tf32, wmma::row_major> b[4];
            #pragma unroll
            for (int ri = 0; ri < 4; ri++)
                wmma::load_matrix_sync(a[ri], as + (wr * 64 + ri * 16) * A_LD + ks * 8, A_LD);
            #pragma unroll
            for (int ci = 0; ci < 4; ci++)
                wmma::load_matrix_sync(b[ci], bs + (ks * 8) * B_LD + wc * 64 + ci * 16, B_LD);
            #pragma unroll
            for (int ri = 0; ri < 4; ri++)
                #pragma unroll
                for (int ci = 0; ci < 4; ci++)
                    wmma::mma_sync(acc[ri][ci], a[ri], b[ci], acc[ri][ci]);
        }
        __syncthreads();
    }

    // ---- Epilogue: two 32-row halves per warp; stage via smem, add E gathers ----
    float* wbuf = smem + wid * (32 * EPI_LD);   // 32x68 per warp (8704 total)
    const int is64 = g_is64;
    #pragma unroll
    for (int h = 0; h < 2; h++) {
        #pragma unroll
        for (int rh = 0; rh < 2; rh++)
            #pragma unroll
            for (int ci = 0; ci < 4; ci++)
                wmma::store_matrix_sync(wbuf + rh * 16 * EPI_LD + ci * 16,
                                        acc[h * 2 + rh][ci], EPI_LD, wmma::mem_row_major);
        __syncwarp();

        const int m = m0 + wr * 64 + h * 32 + lane;
        int i1, i2;
        if (is64) {
            i1 = (int)((const long long*)dfnp)[m] & (MAXLEN - 1);
            i2 = (int)((const long long*)dfap)[m] & (MAXLEN - 1);
        } else {
            i1 = ((const int*)dfnp)[m] & (MAXLEN - 1);
            i2 = ((const int*)dfap)[m] & (MAXLEN - 1);
        }
        const float* e1 = g_E + (size_t)i1 * D_MODEL;
        const float* e2 = g_E + (size_t)i2 * D_MODEL;
        float* orow = out + (size_t)m * D_MODEL;
        const int cbase = n0 + wc * 64;
        #pragma unroll
        for (int cq = 0; cq < 16; cq++) {
            const int c = cbase + cq * 4;
            float4 v  = *(float4*)(wbuf + lane * EPI_LD + cq * 4);
            float4 a1 = *(const float4*)(e1 + c);
            float4 a2 = *(const float4*)(e2 + c);
            v.x += a1.x + a2.x;  v.y += a1.y + a2.y;
            v.z += a1.z + a2.z;  v.w += a1.w + a2.w;
            *(float4*)(orow + c) = v;
        }
        __syncwarp();
    }
    #undef ISSUE_STAGE
}

// ============================================================================
// Host launcher — rank-based classification (robust to size conventions and
// ordering). enc vs W disambiguated on-device; dfn vs dfn_fa symmetric.
// ============================================================================
extern "C" void kernel_launch(void* const* d_in, const int* in_sizes, int n_in,
                              void* d_out, int out_size) {
    int order[16];
    int n = (n_in < 16) ? n_in : 16;
    for (int i = 0; i < n; i++) order[i] = i;
    for (int i = 1; i < n; i++) {
        int key = order[i];
        long long ks = in_sizes[key];
        int j = i - 1;
        while (j >= 0 && (long long)in_sizes[order[j]] > ks) {
            order[j + 1] = order[j];
            j--;
        }
        order[j + 1] = key;
    }

    const void*  dfn;
    const void*  dfa;
    const float* latent;
    const float* cand1;
    const float* cand2;
    const float* bias;

    if (n >= 6) {
        bias   = (const float*)d_in[order[0]];
        dfn    = d_in[order[1]];
        dfa    = d_in[order[2]];
        cand1  = (const float*)d_in[order[3]];
        cand2  = (const float*)d_in[order[4]];
        latent = (const float*)d_in[order[n - 1]];
    } else {
        dfn    = d_in[0];
        dfa    = d_in[1];
        latent = (const float*)d_in[2];
        cand1  = (const float*)d_in[3];
        cand2  = (const float*)d_in[4];
        bias   = (const float*)d_in[5];
    }

    detect_kernel<<<1, 256>>>((const int*)dfn, cand1);
    w2_tf32_kernel<<<1024, 256>>>(cand1, cand2);
    compute_E_kernel<<<dim3(16, 8), 256>>>(cand1, cand2, bias);

    cudaFuncSetAttribute(gemm_wmma, cudaFuncAttributeMaxDynamicSharedMemorySize, SMEM_BYTES);

    dim3 grid(D_MODEL / NCTA, M_TOTAL / MCTA);   // (4, 512), n fastest
    gemm_wmma<<<grid, THREADS, SMEM_BYTES>>>(latent, dfn, dfa, (float*)d_out);
}